// round 9
// baseline (speedup 1.0000x reference)
#include <cuda_runtime.h>
#include <cuda_bf16.h>
#include <cstdint>

#define NN 200000
#define NE 4000000
#define RR 4
#define DD 64
#define NRSEG (NN*RR)
#define GG 64
#define CC 10
#define ZN NN                            // sentinel node -> zero row
#define NES (NE + 3*NRSEG)               // padded edge-list capacity
#define SC_NB ((NRSEG + 1023) / 1024)    // 782 scan blocks
#define SGB ((NE + 1023) / 1024)         // 3907 scatter blocks
#define SLICE ((NRSEG + SGB - 1) / SGB)  // 205 offsets finalized per block
#define NW 61440                         // 3*5*4096 weight elems
#define CH 50176                         // layer chunk (196*256 nodes)

// ---------------- device scratch (no allocations allowed) ----------------
static __device__ __align__(16) int   g_cntlook[NRSEG + 256]; // true counts
static __device__ __align__(16) int   g_off[NRSEG];    // padded per-block partial
static __device__ __align__(16) int   g_off2[NRSEG];   // padded finalized exclusive
static __device__ __align__(16) int   g_bsum[1024];
static __device__ __align__(16) int   g_rank[NE];
static __device__ __align__(16) int   g_sorted[NES];
static __device__ __align__(16) int   g_goff[GG + 1];
static __device__ __align__(16) __nv_bfloat16 g_hA[(NN + 1) * DD];
static __device__ __align__(16) __nv_bfloat16 g_hB[(NN + 1) * DD];
static __device__ __align__(16) __nv_bfloat16 g_M[RR * NN * DD]; // [r][node][64]
static __device__ __align__(16) __nv_bfloat16 g_Wb[NW];          // [l][c][k][e]
static __device__ __align__(16) float g_pp[GG * 4 * DD];

__device__ __forceinline__ void cpa16(uint32_t dst, const void* src, int srcsize) {
    asm volatile("cp.async.ca.shared.global [%0], [%1], 16, %2;"
                 :: "r"(dst), "l"(src), "r"(srcsize));
}

// ---------------- fused: hist(+rank) + h0 + zero rows + weight conversion --
__global__ void k_hist_h0(const int* __restrict__ tgt, const int* __restrict__ et,
                          const int* __restrict__ xop, const int* __restrict__ xcat,
                          const float* __restrict__ opemb, const float* __restrict__ catemb,
                          const float* __restrict__ w1, const float* __restrict__ r1,
                          const float* __restrict__ w2, const float* __restrict__ r2,
                          const float* __restrict__ w3, const float* __restrict__ r3) {
    int i = blockIdx.x * blockDim.x + threadIdx.x;
    if (i < NE) {
        int s = tgt[i] * RR + et[i];
        g_rank[i] = atomicAdd(&g_cntlook[s], 1);
        if (i < NW) { // weight conversion rides along (NW << NE)
            int l = i / 20480, r = i % 20480, c = r / 4096, j = r % 4096;
            const float* w = (l == 0) ? w1 : (l == 1) ? w2 : w3;
            const float* rt = (l == 0) ? r1 : (l == 1) ? r2 : r3;
            float v = (c < 4) ? w[c * 4096 + j] : rt[j];
            g_Wb[i] = __float2bfloat16(v);
        }
    }
    if (i < NN * 32) {
        int n = i >> 5, j = i & 31;
        const float2* oe = (const float2*)opemb;
        const float2* ce = (const float2*)catemb;
        float2 a = oe[xop[n] * 32 + j];
        float2 b = ce[xcat[n] * 32 + j];
        ((__nv_bfloat162*)g_hA)[n * 32 + j] =
            __float22bfloat162_rn(make_float2(a.x + b.x, a.y + b.y));
    } else if (i < NN * 32 + 64) {
        int j = i - NN * 32;
        __nv_bfloat162 z = __float2bfloat162_rn(0.f);
        if (j < 32) ((__nv_bfloat162*)g_hA)[NN * 32 + j] = z;
        else        ((__nv_bfloat162*)g_hB)[NN * 32 + (j - 32)] = z;
    }
}

// ---------------- block-local exclusive scan over PADDED counts -----------
__global__ void k_scan1() {
    __shared__ int sh[1024];
    int t = threadIdx.x;
    int i = blockIdx.x * 1024 + t;
    int v = 0;
    if (i < NRSEG) v = (g_cntlook[i] + 3) & ~3;   // pad to multiple of 4
    sh[t] = v;
    __syncthreads();
    for (int s = 1; s < 1024; s <<= 1) {
        int add = (t >= s) ? sh[t - s] : 0;
        __syncthreads();
        sh[t] += add;
        __syncthreads();
    }
    if (i < NRSEG) g_off[i] = sh[t] - v;
    if (t == 1023) g_bsum[blockIdx.x] = sh[1023];
}

// ---------------- fused: bsum-prefix + finalize + pad-fill + scatter + goff
__global__ __launch_bounds__(256) void k_scatter_goff(const int* __restrict__ srcarr,
                                                      const int* __restrict__ tgt,
                                                      const int* __restrict__ et,
                                                      const int* __restrict__ batch) {
    __shared__ int pre[1024];
    __shared__ int wsum[8];
    int b = blockIdx.x, t = threadIdx.x;
    int x[4];
    int run = 0;
#pragma unroll
    for (int k = 0; k < 4; ++k) {
        int i = t * 4 + k;
        int v = (i < SC_NB) ? g_bsum[i] : 0;
        x[k] = run;
        run += v;
    }
    int lane = t & 31, wp = t >> 5;
    int inc = run;
#pragma unroll
    for (int d = 1; d < 32; d <<= 1) {
        int y = __shfl_up_sync(0xffffffffu, inc, d);
        if (lane >= d) inc += y;
    }
    if (lane == 31) wsum[wp] = inc;
    __syncthreads();
    if (wp == 0) {
        int ws = (lane < 8) ? wsum[lane] : 0;
#pragma unroll
        for (int d = 1; d < 8; d <<= 1) {
            int y = __shfl_up_sync(0xffffffffu, ws, d);
            if (lane >= d) ws += y;
        }
        if (lane < 8) wsum[lane] = ws;
    }
    __syncthreads();
    int excl = inc - run + (wp > 0 ? wsum[wp - 1] : 0);
#pragma unroll
    for (int k = 0; k < 4; ++k) pre[t * 4 + k] = excl + x[k];
    __syncthreads();

    // finalize slice of padded offsets + fill pad slots with sentinel ZN
    if (t < SLICE) {
        int i = b * SLICE + t;
        if (i < NRSEG) {
            int o = g_off[i] + pre[i >> 10];
            g_off2[i] = o;
            int c = g_cntlook[i];
            int pc = (c + 3) & ~3;
            for (int p = c; p < pc; ++p) g_sorted[o + p] = ZN;
        }
    }

    // atomic-free scatter + batch boundaries
#pragma unroll
    for (int k = 0; k < 4; ++k) {
        int e = b * 1024 + k * 256 + t;
        if (e < NE) {
            int s = tgt[e] * RR + et[e];
            g_sorted[g_off[s] + pre[s >> 10] + g_rank[e]] = srcarr[e];
        }
        if (e < NN) {
            int bb = batch[e];
            if (e == 0) {
                for (int g = 0; g <= bb; ++g) g_goff[g] = 0;
            } else {
                int bp = batch[e - 1];
                for (int g = bp + 1; g <= bb; ++g) g_goff[g] = e;
            }
            if (e == NN - 1) {
                for (int g = bb + 1; g <= GG; ++g) g_goff[g] = NN;
            }
        }
    }
}

// ---------------- per-(node,relation) mean aggregation v4 ------------------
// Warp = node; 4 groups of 8 lanes; group g owns relation g.
// Padded segments (sentinel ZN -> zero row) + software-pipelined idx prefetch.
// Processes node range [n0, n0+nCnt).
__global__ __launch_bounds__(256) void k_agg(int inB, int n0, int nCnt) {
    int lw = (blockIdx.x * blockDim.x + threadIdx.x) >> 5;
    int lane = threadIdx.x & 31;
    if (lw >= nCnt) return;
    int gw = n0 + lw;
    int q = lane & 7;
    int g = lane >> 3;
    const __nv_bfloat16* hin = inB ? g_hB : g_hA;

    int pre = 0;
    if (lane < 8) pre = (lane < 4) ? g_off2[gw * RR + lane] : g_cntlook[gw * RR + lane - 4];
    int off_g = __shfl_sync(0xffffffffu, pre, g);
    int cnt_g = __shfl_sync(0xffffffffu, pre, 4 + g);
    int iters_g = (cnt_g + 3) >> 2;
    int im = iters_g;
    im = max(im, __shfl_xor_sync(0xffffffffu, im, 8));
    im = max(im, __shfl_xor_sync(0xffffffffu, im, 16));

    __nv_bfloat162 a0 = __float2bfloat162_rn(0.f);
    __nv_bfloat162 a1 = a0, a2 = a0, a3 = a0;

    bool ld = (q < 4);
    int idx = (ld && 0 < iters_g) ? g_sorted[off_g + q] : ZN;
    for (int it = 0; it < im; ++it) {
        // prefetch next iteration's indices before the dependent shfl chain
        int nxt = (ld && (it + 1) < iters_g) ? g_sorted[off_g + (it + 1) * 4 + q] : ZN;
#pragma unroll
        for (int t = 0; t < 4; ++t) {
            int sn = __shfl_sync(0xffffffffu, idx, (lane & 24) + t);
            uint4 v = *(const uint4*)(hin + sn * 64 + q * 8);
            a0 = __hadd2(a0, *(const __nv_bfloat162*)&v.x);
            a1 = __hadd2(a1, *(const __nv_bfloat162*)&v.y);
            a2 = __hadd2(a2, *(const __nv_bfloat162*)&v.z);
            a3 = __hadd2(a3, *(const __nv_bfloat162*)&v.w);
        }
        idx = nxt;
    }

    float inv = (cnt_g > 0) ? (1.f / (float)cnt_g) : 0.f;
    __nv_bfloat162 o[4];
    float2 f;
    f = __bfloat1622float2(a0); o[0] = __float22bfloat162_rn(make_float2(f.x * inv, f.y * inv));
    f = __bfloat1622float2(a1); o[1] = __float22bfloat162_rn(make_float2(f.x * inv, f.y * inv));
    f = __bfloat1622float2(a2); o[2] = __float22bfloat162_rn(make_float2(f.x * inv, f.y * inv));
    f = __bfloat1622float2(a3); o[3] = __float22bfloat162_rn(make_float2(f.x * inv, f.y * inv));
    *(uint4*)(g_M + (g * NN + gw) * 64 + q * 8) = *(const uint4*)o;
}

// ---------------- tensor-core GEMM with cp.async double buffering ----------
// tile 256 nodes x 64 outputs, K = 5 chunks of 64, 2-stage pipeline.
// Node range offset n0 (chunked so g_M is consumed L2-hot).
#define ASTR 72
#define AS_ELEM (256 * ASTR)
#define BS_ELEM (64 * ASTR)
#define GEMM_SMEM (2 * AS_ELEM * 2 + 2 * BS_ELEM * 2 + 256)
__global__ __launch_bounds__(256) void k_gemm(int inB, int l, int n0,
                                              const float* __restrict__ bias,
                                              int do_relu) {
    extern __shared__ __align__(16) unsigned char dsm[];
    __nv_bfloat16* As = (__nv_bfloat16*)dsm;
    __nv_bfloat16* Bs = (__nv_bfloat16*)(dsm + 2 * AS_ELEM * 2);
    float* biass = (float*)(dsm + 2 * AS_ELEM * 2 + 2 * BS_ELEM * 2);

    const __nv_bfloat16* hin = inB ? g_hB : g_hA;
    __nv_bfloat16* hout = inB ? g_hA : g_hB;
    const __nv_bfloat16* wb = g_Wb + l * 20480;

    int tid = threadIdx.x;
    int lane = tid & 31;
    int wp = tid >> 5;
    int nbase = n0 + blockIdx.x * 256;

    if (tid < 64) biass[tid] = bias[tid];

    float d[2][4][2][4];
#pragma unroll
    for (int rg = 0; rg < 2; ++rg)
#pragma unroll
        for (int t = 0; t < 4; ++t)
#pragma unroll
            for (int s = 0; s < 2; ++s)
#pragma unroll
                for (int i = 0; i < 4; ++i) d[rg][t][s][i] = 0.f;

    uint32_t as_base = (uint32_t)__cvta_generic_to_shared(As);
    uint32_t bs_base = (uint32_t)__cvta_generic_to_shared(Bs);

    auto stage = [&](int c, int buf) {
#pragma unroll
        for (int it = 0; it < 2; ++it) {      // B: 64x64 bf16 = 512 x 16B
            int idx = it * 256 + tid;
            int kk = idx >> 3, e8 = idx & 7;
            uint32_t dst = bs_base + (buf * BS_ELEM + kk * ASTR + e8 * 8) * 2;
            cpa16(dst, wb + c * 4096 + kk * 64 + e8 * 8, 16);
        }
#pragma unroll
        for (int it = 0; it < 8; ++it) {      // A: 256x64 bf16 = 2048 x 16B
            int idx = it * 256 + tid;
            int node = idx >> 3, k8 = idx & 7;
            int gn = nbase + node;
            int gs = gn < NN ? gn : NN - 1;
            const __nv_bfloat16* src = (c < 4) ? (g_M + (c * NN + gs) * 64 + k8 * 8)
                                               : (hin + gs * 64 + k8 * 8);
            uint32_t dst = as_base + (buf * AS_ELEM + node * ASTR + k8 * 8) * 2;
            cpa16(dst, src, gn < NN ? 16 : 0);
        }
    };

    stage(0, 0);
    asm volatile("cp.async.commit_group;");

    for (int c = 0; c < 5; ++c) {
        int buf = c & 1;
        if (c < 4) {
            stage(c + 1, (c + 1) & 1);
            asm volatile("cp.async.commit_group;");
            asm volatile("cp.async.wait_group 1;");
        } else {
            asm volatile("cp.async.wait_group 0;");
        }
        __syncthreads();

        uint32_t ab = as_base + buf * AS_ELEM * 2;
        uint32_t bb = bs_base + buf * BS_ELEM * 2;
#pragma unroll
        for (int ks = 0; ks < 4; ++ks) {
            uint32_t a[2][4];
#pragma unroll
            for (int rg = 0; rg < 2; ++rg) {
                uint32_t aaddr = ab +
                    ((wp * 32 + rg * 16 + (lane & 15)) * ASTR + ks * 16 + ((lane >> 4) << 3)) * 2;
                asm volatile(
                    "ldmatrix.sync.aligned.m8n8.x4.shared.b16 {%0,%1,%2,%3}, [%4];"
                    : "=r"(a[rg][0]), "=r"(a[rg][1]), "=r"(a[rg][2]), "=r"(a[rg][3])
                    : "r"(aaddr));
            }
#pragma unroll
            for (int t = 0; t < 4; ++t) {
                uint32_t b0, b1, b2, b3;
                uint32_t baddr = bb +
                    ((ks * 16 + (lane & 15)) * ASTR + t * 16 + ((lane >> 4) << 3)) * 2;
                asm volatile(
                    "ldmatrix.sync.aligned.m8n8.x4.trans.shared.b16 {%0,%1,%2,%3}, [%4];"
                    : "=r"(b0), "=r"(b1), "=r"(b2), "=r"(b3) : "r"(baddr));
#pragma unroll
                for (int rg = 0; rg < 2; ++rg) {
                    asm volatile(
                        "mma.sync.aligned.m16n8k16.row.col.f32.bf16.bf16.f32 "
                        "{%0,%1,%2,%3}, {%4,%5,%6,%7}, {%8,%9}, {%0,%1,%2,%3};"
                        : "+f"(d[rg][t][0][0]), "+f"(d[rg][t][0][1]),
                          "+f"(d[rg][t][0][2]), "+f"(d[rg][t][0][3])
                        : "r"(a[rg][0]), "r"(a[rg][1]), "r"(a[rg][2]), "r"(a[rg][3]),
                          "r"(b0), "r"(b1));
                    asm volatile(
                        "mma.sync.aligned.m16n8k16.row.col.f32.bf16.bf16.f32 "
                        "{%0,%1,%2,%3}, {%4,%5,%6,%7}, {%8,%9}, {%0,%1,%2,%3};"
                        : "+f"(d[rg][t][1][0]), "+f"(d[rg][t][1][1]),
                          "+f"(d[rg][t][1][2]), "+f"(d[rg][t][1][3])
                        : "r"(a[rg][0]), "r"(a[rg][1]), "r"(a[rg][2]), "r"(a[rg][3]),
                          "r"(b2), "r"(b3));
                }
            }
        }
        __syncthreads();
    }

    // epilogue: bias + relu, bf16 store
    __nv_bfloat162* hout2 = (__nv_bfloat162*)hout;
#pragma unroll
    for (int rg = 0; rg < 2; ++rg) {
        int r0 = nbase + wp * 32 + rg * 16 + (lane >> 2);
        int r1 = r0 + 8;
#pragma unroll
        for (int t = 0; t < 4; ++t) {
#pragma unroll
            for (int s = 0; s < 2; ++s) {
                int n0c = t * 16 + s * 8 + (lane & 3) * 2;
                float bx = biass[n0c], by = biass[n0c + 1];
                float v0 = d[rg][t][s][0] + bx, v1 = d[rg][t][s][1] + by;
                float v2 = d[rg][t][s][2] + bx, v3 = d[rg][t][s][3] + by;
                if (do_relu) {
                    v0 = fmaxf(v0, 0.f); v1 = fmaxf(v1, 0.f);
                    v2 = fmaxf(v2, 0.f); v3 = fmaxf(v3, 0.f);
                }
                if (r0 < NN)
                    hout2[r0 * 32 + n0c / 2] = __float22bfloat162_rn(make_float2(v0, v1));
                if (r1 < NN)
                    hout2[r1 * 32 + n0c / 2] = __float22bfloat162_rn(make_float2(v2, v3));
            }
        }
    }
}

// ---------------- pooling: (graph, quarter) partial sums -------------------
__global__ void k_pool(int inB) {
    const __nv_bfloat16* h = inB ? g_hB : g_hA;
    int g = blockIdx.x, qt = blockIdx.y;
    int st = g_goff[g], en = g_goff[g + 1];
    int len = en - st;
    int n0 = st + (len * qt) / 4;
    int n1 = st + (len * (qt + 1)) / 4;
    int d = threadIdx.x & 63;
    int y = threadIdx.x >> 6;
    float acc = 0.f;
    for (int n = n0 + y; n < n1; n += 4) acc += __bfloat162float(h[n * DD + d]);
    __shared__ float red[4][64];
    red[y][d] = acc;
    __syncthreads();
    if (y == 0)
        g_pp[(g * 4 + qt) * DD + d] = red[0][d] + red[1][d] + red[2][d] + red[3][d];
}

// ---------------- MLP head + log_softmax ------------------------------------
__global__ void k_head(const float* __restrict__ fc1w, const float* __restrict__ fc1b,
                       const float* __restrict__ fc2w, const float* __restrict__ fc2b,
                       float* __restrict__ out) {
    __shared__ float w1s[DD * DD];
    __shared__ float w2s[DD * CC];
    __shared__ float b1s[DD];
    __shared__ float b2s[CC];
    int t = threadIdx.x; // 64 threads
    for (int i = t; i < DD * DD; i += 64) w1s[i] = fc1w[i];
    for (int i = t; i < DD * CC; i += 64) w2s[i] = fc2w[i];
    if (t < DD) b1s[t] = fc1b[t];
    if (t < CC) b2s[t] = fc2b[t];
    __syncthreads();
    int g = t;
    int cnt = g_goff[g + 1] - g_goff[g];
    float inv = 1.f / (float)(cnt > 0 ? cnt : 1);
    float p[DD];
#pragma unroll
    for (int d = 0; d < DD; ++d)
        p[d] = (g_pp[(g * 4 + 0) * DD + d] + g_pp[(g * 4 + 1) * DD + d] +
                g_pp[(g * 4 + 2) * DD + d] + g_pp[(g * 4 + 3) * DD + d]) * inv;
    float t1[DD];
    for (int e = 0; e < DD; ++e) {
        float a = b1s[e];
#pragma unroll
        for (int d = 0; d < DD; ++d) a += p[d] * w1s[d * DD + e];
        t1[e] = fmaxf(a, 0.f);
    }
    float lg[CC];
    for (int c = 0; c < CC; ++c) {
        float a = b2s[c];
#pragma unroll
        for (int e = 0; e < DD; ++e) a += t1[e] * w2s[e * CC + c];
        lg[c] = a;
    }
    float m = lg[0];
    for (int c = 1; c < CC; ++c) m = fmaxf(m, lg[c]);
    float s = 0.f;
    for (int c = 0; c < CC; ++c) s += expf(lg[c] - m);
    float ls = logf(s);
    for (int c = 0; c < CC; ++c) out[g * CC + c] = lg[c] - m - ls;
}

// ---------------- launch --------------------------------------------------
extern "C" void kernel_launch(void* const* d_in, const int* in_sizes, int n_in,
                              void* d_out, int out_size) {
    const int* x_op = (const int*)d_in[0];
    const int* x_cat = (const int*)d_in[1];
    const int* ei = (const int*)d_in[2];
    const int* etyp = (const int*)d_in[3];
    const int* batch = (const int*)d_in[4];
    const float* opemb = (const float*)d_in[5];
    const float* catemb = (const float*)d_in[6];
    const float* W[3] = {(const float*)d_in[7], (const float*)d_in[10], (const float*)d_in[13]};
    const float* Rt[3] = {(const float*)d_in[8], (const float*)d_in[11], (const float*)d_in[14]};
    const float* Bi[3] = {(const float*)d_in[9], (const float*)d_in[12], (const float*)d_in[15]};
    const float* fc1w = (const float*)d_in[16];
    const float* fc1b = (const float*)d_in[17];
    const float* fc2w = (const float*)d_in[18];
    const float* fc2b = (const float*)d_in[19];
    float* out = (float*)d_out;
    const int* src = ei;
    const int* tgt = ei + NE;

    cudaFuncSetAttribute(k_gemm, cudaFuncAttributeMaxDynamicSharedMemorySize, GEMM_SMEM);

    // zero counts via memset node
    void* cl_ptr = nullptr;
    cudaGetSymbolAddress(&cl_ptr, g_cntlook);
    cudaMemsetAsync(cl_ptr, 0, (NRSEG + 256) * sizeof(int), 0);

    k_hist_h0<<<(NN * 32 + 64 + 255) / 256, 256>>>(tgt, etyp, x_op, x_cat, opemb, catemb,
                                                   W[0], Rt[0], W[1], Rt[1], W[2], Rt[2]);
    k_scan1<<<SC_NB, 1024>>>();
    k_scatter_goff<<<SGB, 256>>>(src, tgt, etyp, batch);

    // 3 RGCN layers, chunked so g_M slices are consumed L2-hot
    for (int l = 0; l < 3; ++l) {
        int inB = l & 1;
        for (int n0 = 0; n0 < NN; n0 += CH) {
            int nCnt = (NN - n0 < CH) ? (NN - n0) : CH;
            k_agg<<<(nCnt * 32 + 255) / 256, 256>>>(inB, n0, nCnt);
            k_gemm<<<(nCnt + 255) / 256, 256, GEMM_SMEM>>>(inB, l, n0, Bi[l], (l < 2) ? 1 : 0);
        }
    }

    k_pool<<<dim3(GG, 4), 256>>>(1); // final h is in g_hB
    k_head<<<1, 64>>>(fc1w, fc1b, fc2w, fc2b, out);
}

// round 10
// speedup vs baseline: 1.1695x; 1.1695x over previous
#include <cuda_runtime.h>
#include <cuda_bf16.h>
#include <cstdint>

#define NN 200000
#define NE 4000000
#define RR 4
#define DD 64
#define NRSEG (NN*RR)
#define GG 64
#define CC 10
#define ZN NN                            // sentinel node -> zero row
#define NES (NE + 3*NRSEG)               // padded edge-list capacity
#define SC_NB ((NRSEG + 1023) / 1024)    // 782 scan blocks
#define SGB ((NE + 1023) / 1024)         // 3907 scatter blocks
#define SLICE ((NRSEG + SGB - 1) / SGB)  // 205 offsets finalized per block
#define NW 61440                         // 3*5*4096 weight elems

// ---------------- device scratch (no allocations allowed) ----------------
static __device__ __align__(16) int   g_cntlook[NRSEG + 256]; // true counts
static __device__ __align__(16) int   g_off[NRSEG];    // padded per-block partial
static __device__ __align__(16) int   g_off2[NRSEG];   // padded finalized exclusive
static __device__ __align__(16) int   g_bsum[1024];
static __device__ __align__(16) int   g_rank[NE];
static __device__ __align__(16) int   g_sorted[NES];
static __device__ __align__(16) int   g_goff[GG + 1];
static __device__ __align__(16) __nv_bfloat16 g_hA[(NN + 1) * DD];
static __device__ __align__(16) __nv_bfloat16 g_hB[(NN + 1) * DD];
static __device__ __align__(16) __nv_bfloat16 g_M[RR * NN * DD]; // [r][node][64]
static __device__ __align__(16) __nv_bfloat16 g_Wb[NW];          // [l][c][k][e]
static __device__ __align__(16) float g_pp[GG * 4 * DD];

__device__ __forceinline__ void cpa16(uint32_t dst, const void* src, int srcsize) {
    asm volatile("cp.async.ca.shared.global [%0], [%1], 16, %2;"
                 :: "r"(dst), "l"(src), "r"(srcsize));
}

// ---------------- fused: hist(+rank) + h0 + zero rows + weight conversion --
__global__ void k_hist_h0(const int* __restrict__ tgt, const int* __restrict__ et,
                          const int* __restrict__ xop, const int* __restrict__ xcat,
                          const float* __restrict__ opemb, const float* __restrict__ catemb,
                          const float* __restrict__ w1, const float* __restrict__ r1,
                          const float* __restrict__ w2, const float* __restrict__ r2,
                          const float* __restrict__ w3, const float* __restrict__ r3) {
    int i = blockIdx.x * blockDim.x + threadIdx.x;
    if (i < NE) {
        int s = tgt[i] * RR + et[i];
        g_rank[i] = atomicAdd(&g_cntlook[s], 1);
        if (i < NW) { // weight conversion rides along (NW << NE)
            int l = i / 20480, r = i % 20480, c = r / 4096, j = r % 4096;
            const float* w = (l == 0) ? w1 : (l == 1) ? w2 : w3;
            const float* rt = (l == 0) ? r1 : (l == 1) ? r2 : r3;
            float v = (c < 4) ? w[c * 4096 + j] : rt[j];
            g_Wb[i] = __float2bfloat16(v);
        }
    }
    if (i < NN * 32) {
        int n = i >> 5, j = i & 31;
        const float2* oe = (const float2*)opemb;
        const float2* ce = (const float2*)catemb;
        float2 a = oe[xop[n] * 32 + j];
        float2 b = ce[xcat[n] * 32 + j];
        ((__nv_bfloat162*)g_hA)[n * 32 + j] =
            __float22bfloat162_rn(make_float2(a.x + b.x, a.y + b.y));
    } else if (i < NN * 32 + 64) {
        int j = i - NN * 32;
        __nv_bfloat162 z = __float2bfloat162_rn(0.f);
        if (j < 32) ((__nv_bfloat162*)g_hA)[NN * 32 + j] = z;
        else        ((__nv_bfloat162*)g_hB)[NN * 32 + (j - 32)] = z;
    }
}

// ---------------- block-local exclusive scan over PADDED counts -----------
__global__ void k_scan1() {
    __shared__ int sh[1024];
    int t = threadIdx.x;
    int i = blockIdx.x * 1024 + t;
    int v = 0;
    if (i < NRSEG) v = (g_cntlook[i] + 3) & ~3;   // pad to multiple of 4
    sh[t] = v;
    __syncthreads();
    for (int s = 1; s < 1024; s <<= 1) {
        int add = (t >= s) ? sh[t - s] : 0;
        __syncthreads();
        sh[t] += add;
        __syncthreads();
    }
    if (i < NRSEG) g_off[i] = sh[t] - v;
    if (t == 1023) g_bsum[blockIdx.x] = sh[1023];
}

// ---------------- fused: bsum-prefix + finalize + pad-fill + scatter + goff
__global__ __launch_bounds__(256) void k_scatter_goff(const int* __restrict__ srcarr,
                                                      const int* __restrict__ tgt,
                                                      const int* __restrict__ et,
                                                      const int* __restrict__ batch) {
    __shared__ int pre[1024];
    __shared__ int wsum[8];
    int b = blockIdx.x, t = threadIdx.x;
    int x[4];
    int run = 0;
#pragma unroll
    for (int k = 0; k < 4; ++k) {
        int i = t * 4 + k;
        int v = (i < SC_NB) ? g_bsum[i] : 0;
        x[k] = run;
        run += v;
    }
    int lane = t & 31, wp = t >> 5;
    int inc = run;
#pragma unroll
    for (int d = 1; d < 32; d <<= 1) {
        int y = __shfl_up_sync(0xffffffffu, inc, d);
        if (lane >= d) inc += y;
    }
    if (lane == 31) wsum[wp] = inc;
    __syncthreads();
    if (wp == 0) {
        int ws = (lane < 8) ? wsum[lane] : 0;
#pragma unroll
        for (int d = 1; d < 8; d <<= 1) {
            int y = __shfl_up_sync(0xffffffffu, ws, d);
            if (lane >= d) ws += y;
        }
        if (lane < 8) wsum[lane] = ws;
    }
    __syncthreads();
    int excl = inc - run + (wp > 0 ? wsum[wp - 1] : 0);
#pragma unroll
    for (int k = 0; k < 4; ++k) pre[t * 4 + k] = excl + x[k];
    __syncthreads();

    // finalize slice of padded offsets + fill pad slots with sentinel ZN
    if (t < SLICE) {
        int i = b * SLICE + t;
        if (i < NRSEG) {
            int o = g_off[i] + pre[i >> 10];
            g_off2[i] = o;
            int c = g_cntlook[i];
            int pc = (c + 3) & ~3;
            for (int p = c; p < pc; ++p) g_sorted[o + p] = ZN;
        }
    }

    // atomic-free scatter + batch boundaries
#pragma unroll
    for (int k = 0; k < 4; ++k) {
        int e = b * 1024 + k * 256 + t;
        if (e < NE) {
            int s = tgt[e] * RR + et[e];
            g_sorted[g_off[s] + pre[s >> 10] + g_rank[e]] = srcarr[e];
        }
        if (e < NN) {
            int bb = batch[e];
            if (e == 0) {
                for (int g = 0; g <= bb; ++g) g_goff[g] = 0;
            } else {
                int bp = batch[e - 1];
                for (int g = bp + 1; g <= bb; ++g) g_goff[g] = e;
            }
            if (e == NN - 1) {
                for (int g = bb + 1; g <= GG; ++g) g_goff[g] = NN;
            }
        }
    }
}

// ---------------- per-(node,relation) mean aggregation v5 ------------------
// Warp = node; 4 groups of 8 lanes; group g owns relation g.
// Padded segments (off % 4 == 0) -> each group loads its 4 edge indices as
// ONE aligned int4 (same addr across 8 lanes = L1 broadcast). No shfl in the
// inner loop; next int4 prefetched before the dependent row loads.
__global__ __launch_bounds__(256) void k_agg(int inB) {
    int gw = (blockIdx.x * blockDim.x + threadIdx.x) >> 5;
    int lane = threadIdx.x & 31;
    if (gw >= NN) return;
    int q = lane & 7;
    int g = lane >> 3;
    const __nv_bfloat16* hin = inB ? g_hB : g_hA;

    int off_g = g_off2[gw * RR + g];      // 8-lane broadcast load
    int cnt_g = g_cntlook[gw * RR + g];   // 8-lane broadcast load
    int iters_g = (cnt_g + 3) >> 2;
    int im = iters_g;
    im = max(im, __shfl_xor_sync(0xffffffffu, im, 8));
    im = max(im, __shfl_xor_sync(0xffffffffu, im, 16));

    __nv_bfloat162 a0 = __float2bfloat162_rn(0.f);
    __nv_bfloat162 a1 = a0, a2 = a0, a3 = a0;

    const int4* ip = (const int4*)(g_sorted + off_g);  // off_g % 4 == 0
    const int4 zf = make_int4(ZN, ZN, ZN, ZN);
    int4 i4 = (0 < iters_g) ? ip[0] : zf;
    for (int it = 0; it < im; ++it) {
        int4 nxt = ((it + 1) < iters_g) ? ip[it + 1] : zf;
#pragma unroll
        for (int t = 0; t < 4; ++t) {
            int sn = (t == 0) ? i4.x : (t == 1) ? i4.y : (t == 2) ? i4.z : i4.w;
            uint4 v = *(const uint4*)(hin + sn * 64 + q * 8);
            a0 = __hadd2(a0, *(const __nv_bfloat162*)&v.x);
            a1 = __hadd2(a1, *(const __nv_bfloat162*)&v.y);
            a2 = __hadd2(a2, *(const __nv_bfloat162*)&v.z);
            a3 = __hadd2(a3, *(const __nv_bfloat162*)&v.w);
        }
        i4 = nxt;
    }

    float inv = (cnt_g > 0) ? (1.f / (float)cnt_g) : 0.f;
    __nv_bfloat162 o[4];
    float2 f;
    f = __bfloat1622float2(a0); o[0] = __float22bfloat162_rn(make_float2(f.x * inv, f.y * inv));
    f = __bfloat1622float2(a1); o[1] = __float22bfloat162_rn(make_float2(f.x * inv, f.y * inv));
    f = __bfloat1622float2(a2); o[2] = __float22bfloat162_rn(make_float2(f.x * inv, f.y * inv));
    f = __bfloat1622float2(a3); o[3] = __float22bfloat162_rn(make_float2(f.x * inv, f.y * inv));
    *(uint4*)(g_M + (g * NN + gw) * 64 + q * 8) = *(const uint4*)o;
}

// ---------------- tensor-core GEMM with cp.async double buffering ----------
// tile 256 nodes x 64 outputs, K = 5 chunks of 64, 2-stage pipeline.
#define ASTR 72
#define AS_ELEM (256 * ASTR)
#define BS_ELEM (64 * ASTR)
#define GEMM_SMEM (2 * AS_ELEM * 2 + 2 * BS_ELEM * 2 + 256)
__global__ __launch_bounds__(256) void k_gemm(int inB, int l,
                                              const float* __restrict__ bias,
                                              int do_relu) {
    extern __shared__ __align__(16) unsigned char dsm[];
    __nv_bfloat16* As = (__nv_bfloat16*)dsm;
    __nv_bfloat16* Bs = (__nv_bfloat16*)(dsm + 2 * AS_ELEM * 2);
    float* biass = (float*)(dsm + 2 * AS_ELEM * 2 + 2 * BS_ELEM * 2);

    const __nv_bfloat16* hin = inB ? g_hB : g_hA;
    __nv_bfloat16* hout = inB ? g_hA : g_hB;
    const __nv_bfloat16* wb = g_Wb + l * 20480;

    int tid = threadIdx.x;
    int lane = tid & 31;
    int wp = tid >> 5;
    int nbase = blockIdx.x * 256;

    if (tid < 64) biass[tid] = bias[tid];

    float d[2][4][2][4];
#pragma unroll
    for (int rg = 0; rg < 2; ++rg)
#pragma unroll
        for (int t = 0; t < 4; ++t)
#pragma unroll
            for (int s = 0; s < 2; ++s)
#pragma unroll
                for (int i = 0; i < 4; ++i) d[rg][t][s][i] = 0.f;

    uint32_t as_base = (uint32_t)__cvta_generic_to_shared(As);
    uint32_t bs_base = (uint32_t)__cvta_generic_to_shared(Bs);

    auto stage = [&](int c, int buf) {
#pragma unroll
        for (int it = 0; it < 2; ++it) {      // B: 64x64 bf16 = 512 x 16B
            int idx = it * 256 + tid;
            int kk = idx >> 3, e8 = idx & 7;
            uint32_t dst = bs_base + (buf * BS_ELEM + kk * ASTR + e8 * 8) * 2;
            cpa16(dst, wb + c * 4096 + kk * 64 + e8 * 8, 16);
        }
#pragma unroll
        for (int it = 0; it < 8; ++it) {      // A: 256x64 bf16 = 2048 x 16B
            int idx = it * 256 + tid;
            int node = idx >> 3, k8 = idx & 7;
            int gn = nbase + node;
            int gs = gn < NN ? gn : NN - 1;
            const __nv_bfloat16* src = (c < 4) ? (g_M + (c * NN + gs) * 64 + k8 * 8)
                                               : (hin + gs * 64 + k8 * 8);
            uint32_t dst = as_base + (buf * AS_ELEM + node * ASTR + k8 * 8) * 2;
            cpa16(dst, src, gn < NN ? 16 : 0);
        }
    };

    stage(0, 0);
    asm volatile("cp.async.commit_group;");

    for (int c = 0; c < 5; ++c) {
        int buf = c & 1;
        if (c < 4) {
            stage(c + 1, (c + 1) & 1);
            asm volatile("cp.async.commit_group;");
            asm volatile("cp.async.wait_group 1;");
        } else {
            asm volatile("cp.async.wait_group 0;");
        }
        __syncthreads();

        uint32_t ab = as_base + buf * AS_ELEM * 2;
        uint32_t bb = bs_base + buf * BS_ELEM * 2;
#pragma unroll
        for (int ks = 0; ks < 4; ++ks) {
            uint32_t a[2][4];
#pragma unroll
            for (int rg = 0; rg < 2; ++rg) {
                uint32_t aaddr = ab +
                    ((wp * 32 + rg * 16 + (lane & 15)) * ASTR + ks * 16 + ((lane >> 4) << 3)) * 2;
                asm volatile(
                    "ldmatrix.sync.aligned.m8n8.x4.shared.b16 {%0,%1,%2,%3}, [%4];"
                    : "=r"(a[rg][0]), "=r"(a[rg][1]), "=r"(a[rg][2]), "=r"(a[rg][3])
                    : "r"(aaddr));
            }
#pragma unroll
            for (int t = 0; t < 4; ++t) {
                uint32_t b0, b1, b2, b3;
                uint32_t baddr = bb +
                    ((ks * 16 + (lane & 15)) * ASTR + t * 16 + ((lane >> 4) << 3)) * 2;
                asm volatile(
                    "ldmatrix.sync.aligned.m8n8.x4.trans.shared.b16 {%0,%1,%2,%3}, [%4];"
                    : "=r"(b0), "=r"(b1), "=r"(b2), "=r"(b3) : "r"(baddr));
#pragma unroll
                for (int rg = 0; rg < 2; ++rg) {
                    asm volatile(
                        "mma.sync.aligned.m16n8k16.row.col.f32.bf16.bf16.f32 "
                        "{%0,%1,%2,%3}, {%4,%5,%6,%7}, {%8,%9}, {%0,%1,%2,%3};"
                        : "+f"(d[rg][t][0][0]), "+f"(d[rg][t][0][1]),
                          "+f"(d[rg][t][0][2]), "+f"(d[rg][t][0][3])
                        : "r"(a[rg][0]), "r"(a[rg][1]), "r"(a[rg][2]), "r"(a[rg][3]),
                          "r"(b0), "r"(b1));
                    asm volatile(
                        "mma.sync.aligned.m16n8k16.row.col.f32.bf16.bf16.f32 "
                        "{%0,%1,%2,%3}, {%4,%5,%6,%7}, {%8,%9}, {%0,%1,%2,%3};"
                        : "+f"(d[rg][t][1][0]), "+f"(d[rg][t][1][1]),
                          "+f"(d[rg][t][1][2]), "+f"(d[rg][t][1][3])
                        : "r"(a[rg][0]), "r"(a[rg][1]), "r"(a[rg][2]), "r"(a[rg][3]),
                          "r"(b2), "r"(b3));
                }
            }
        }
        __syncthreads();
    }

    // epilogue: bias + relu, bf16 store
    __nv_bfloat162* hout2 = (__nv_bfloat162*)hout;
#pragma unroll
    for (int rg = 0; rg < 2; ++rg) {
        int r0 = nbase + wp * 32 + rg * 16 + (lane >> 2);
        int r1 = r0 + 8;
#pragma unroll
        for (int t = 0; t < 4; ++t) {
#pragma unroll
            for (int s = 0; s < 2; ++s) {
                int n0 = t * 16 + s * 8 + (lane & 3) * 2;
                float bx = biass[n0], by = biass[n0 + 1];
                float v0 = d[rg][t][s][0] + bx, v1 = d[rg][t][s][1] + by;
                float v2 = d[rg][t][s][2] + bx, v3 = d[rg][t][s][3] + by;
                if (do_relu) {
                    v0 = fmaxf(v0, 0.f); v1 = fmaxf(v1, 0.f);
                    v2 = fmaxf(v2, 0.f); v3 = fmaxf(v3, 0.f);
                }
                if (r0 < NN)
                    hout2[r0 * 32 + n0 / 2] = __float22bfloat162_rn(make_float2(v0, v1));
                if (r1 < NN)
                    hout2[r1 * 32 + n0 / 2] = __float22bfloat162_rn(make_float2(v2, v3));
            }
        }
    }
}

// ---------------- pooling: (graph, quarter) partial sums -------------------
__global__ void k_pool(int inB) {
    const __nv_bfloat16* h = inB ? g_hB : g_hA;
    int g = blockIdx.x, qt = blockIdx.y;
    int st = g_goff[g], en = g_goff[g + 1];
    int len = en - st;
    int n0 = st + (len * qt) / 4;
    int n1 = st + (len * (qt + 1)) / 4;
    int d = threadIdx.x & 63;
    int y = threadIdx.x >> 6;
    float acc = 0.f;
    for (int n = n0 + y; n < n1; n += 4) acc += __bfloat162float(h[n * DD + d]);
    __shared__ float red[4][64];
    red[y][d] = acc;
    __syncthreads();
    if (y == 0)
        g_pp[(g * 4 + qt) * DD + d] = red[0][d] + red[1][d] + red[2][d] + red[3][d];
}

// ---------------- MLP head + log_softmax ------------------------------------
__global__ void k_head(const float* __restrict__ fc1w, const float* __restrict__ fc1b,
                       const float* __restrict__ fc2w, const float* __restrict__ fc2b,
                       float* __restrict__ out) {
    __shared__ float w1s[DD * DD];
    __shared__ float w2s[DD * CC];
    __shared__ float b1s[DD];
    __shared__ float b2s[CC];
    int t = threadIdx.x; // 64 threads
    for (int i = t; i < DD * DD; i += 64) w1s[i] = fc1w[i];
    for (int i = t; i < DD * CC; i += 64) w2s[i] = fc2w[i];
    if (t < DD) b1s[t] = fc1b[t];
    if (t < CC) b2s[t] = fc2b[t];
    __syncthreads();
    int g = t;
    int cnt = g_goff[g + 1] - g_goff[g];
    float inv = 1.f / (float)(cnt > 0 ? cnt : 1);
    float p[DD];
#pragma unroll
    for (int d = 0; d < DD; ++d)
        p[d] = (g_pp[(g * 4 + 0) * DD + d] + g_pp[(g * 4 + 1) * DD + d] +
                g_pp[(g * 4 + 2) * DD + d] + g_pp[(g * 4 + 3) * DD + d]) * inv;
    float t1[DD];
    for (int e = 0; e < DD; ++e) {
        float a = b1s[e];
#pragma unroll
        for (int d = 0; d < DD; ++d) a += p[d] * w1s[d * DD + e];
        t1[e] = fmaxf(a, 0.f);
    }
    float lg[CC];
    for (int c = 0; c < CC; ++c) {
        float a = b2s[c];
#pragma unroll
        for (int e = 0; e < DD; ++e) a += t1[e] * w2s[e * CC + c];
        lg[c] = a;
    }
    float m = lg[0];
    for (int c = 1; c < CC; ++c) m = fmaxf(m, lg[c]);
    float s = 0.f;
    for (int c = 0; c < CC; ++c) s += expf(lg[c] - m);
    float ls = logf(s);
    for (int c = 0; c < CC; ++c) out[g * CC + c] = lg[c] - m - ls;
}

// ---------------- launch --------------------------------------------------
extern "C" void kernel_launch(void* const* d_in, const int* in_sizes, int n_in,
                              void* d_out, int out_size) {
    const int* x_op = (const int*)d_in[0];
    const int* x_cat = (const int*)d_in[1];
    const int* ei = (const int*)d_in[2];
    const int* etyp = (const int*)d_in[3];
    const int* batch = (const int*)d_in[4];
    const float* opemb = (const float*)d_in[5];
    const float* catemb = (const float*)d_in[6];
    const float* W[3] = {(const float*)d_in[7], (const float*)d_in[10], (const float*)d_in[13]};
    const float* Rt[3] = {(const float*)d_in[8], (const float*)d_in[11], (const float*)d_in[14]};
    const float* Bi[3] = {(const float*)d_in[9], (const float*)d_in[12], (const float*)d_in[15]};
    const float* fc1w = (const float*)d_in[16];
    const float* fc1b = (const float*)d_in[17];
    const float* fc2w = (const float*)d_in[18];
    const float* fc2b = (const float*)d_in[19];
    float* out = (float*)d_out;
    const int* src = ei;
    const int* tgt = ei + NE;

    cudaFuncSetAttribute(k_gemm, cudaFuncAttributeMaxDynamicSharedMemorySize, GEMM_SMEM);

    // zero counts via memset node
    void* cl_ptr = nullptr;
    cudaGetSymbolAddress(&cl_ptr, g_cntlook);
    cudaMemsetAsync(cl_ptr, 0, (NRSEG + 256) * sizeof(int), 0);

    k_hist_h0<<<(NN * 32 + 64 + 255) / 256, 256>>>(tgt, etyp, x_op, x_cat, opemb, catemb,
                                                   W[0], Rt[0], W[1], Rt[1], W[2], Rt[2]);
    k_scan1<<<SC_NB, 1024>>>();
    k_scatter_goff<<<SGB, 256>>>(src, tgt, etyp, batch);

    // 3 RGCN layers, ping-pong hA/hB (unchunked — R9 chunking regressed)
    for (int l = 0; l < 3; ++l) {
        int inB = l & 1;
        k_agg<<<(NN * 32 + 255) / 256, 256>>>(inB);
        k_gemm<<<(NN + 255) / 256, 256, GEMM_SMEM>>>(inB, l, Bi[l], (l < 2) ? 1 : 0);
    }

    k_pool<<<dim3(GG, 4), 256>>>(1); // final h is in g_hB
    k_head<<<1, 64>>>(fc1w, fc1b, fc2w, fc2b, out);
}